// round 5
// baseline (speedup 1.0000x reference)
#include <cuda_runtime.h>

#define TB   384        // threads per block (3 s-groups)
#define HB   128        // batch elements per block
#define HD   10         // HDIM
#define MSZ  41         // M
#define MAXP 256        // max s-pairs (S<=512)
#define P2   21         // k-pairs for conv2 (ceil(41/2))

typedef unsigned long long u64;

// rec1: per s-pair j (s=2j,2j+1), 96 floats:
//  [0..2] byte-offsets (k1,k2,k3)*2048 for even s, [3] pad
//  [4..6] same for odd s, [7] pad
//  [8,9]=C.re/2 (e,o) [10,11]=C.im/2 (e,o) [12..15] pad
//  weights at [16 + o*8]: Ws.re(e,o), Ws.im(e,o), Wd.re(e,o), Wd.im(e,o)
__device__ float g_rec1[MAXP * 96];
// rec2: per k-pair j, 80 floats: [o*8]: Ws2.re(e,o), Ws2.im(e,o), Wd2.re(e,o), Wd2.im(e,o)
__device__ float g_rec2[P2 * 80];

__device__ __forceinline__ u64 pk(float lo, float hi) {
    u64 r; asm("mov.b64 %0,{%1,%2};" : "=l"(r) : "f"(lo), "f"(hi)); return r;
}
__device__ __forceinline__ float2 upk(u64 v) {
    float2 f; asm("mov.b64 {%0,%1},%2;" : "=f"(f.x), "=f"(f.y) : "l"(v)); return f;
}
__device__ __forceinline__ void fma2(u64 &a, u64 x, u64 y) {
    asm("fma.rn.f32x2 %0,%1,%2,%0;" : "+l"(a) : "l"(x), "l"(y));
}
__device__ __forceinline__ u64 mul2(u64 x, u64 y) {
    u64 r; asm("mul.rn.f32x2 %0,%1,%2;" : "=l"(r) : "l"(x), "l"(y)); return r;
}
__device__ __forceinline__ u64 ng(u64 v) { return v ^ 0x8000000080000000ULL; }

__global__ void prep_kernel(const float* __restrict__ pbc_C,
                            const float* __restrict__ W1,
                            const float* __restrict__ W2,
                            const int*   __restrict__ m_idx,
                            const int*   __restrict__ n_idx,
                            int S) {
    int j = blockIdx.x * blockDim.x + threadIdx.x;
    int P1 = (S + 1) / 2;
    const int c = MSZ / 2;
    if (j < P1) {
        float* r = g_rec1 + j * 96;
        r[3] = 0.f; r[7] = 0.f;
        r[12] = r[13] = r[14] = r[15] = 0.f;
#pragma unroll
        for (int h = 0; h < 2; h++) {
            int s = 2 * j + h;
            bool v = (s < S);
            int m = v ? m_idx[s] : 0;
            int n = v ? n_idx[s] : 0;
            r[4 * h + 0] = __int_as_float(v ? (c + m) * 2048 : 0);
            r[4 * h + 1] = __int_as_float(v ? (c + m + n) * 2048 : 0);
            r[4 * h + 2] = __int_as_float(v ? (c + n) * 2048 : 0);
            r[8 + h]  = v ? 0.5f * pbc_C[2 * s + 0] : 0.f;
            r[10 + h] = v ? 0.5f * pbc_C[2 * s + 1] : 0.f;
#pragma unroll
            for (int o = 0; o < HD; o++) {
                float war = v ? W1[((2 * o) * S + s) * 2 + 0] : 0.f;
                float wai = v ? W1[((2 * o) * S + s) * 2 + 1] : 0.f;
                float wbr = v ? W1[((2 * o + 1) * S + s) * 2 + 0] : 0.f;
                float wbi = v ? W1[((2 * o + 1) * S + s) * 2 + 1] : 0.f;
                int base = 16 + o * 8;
                r[base + 0 + h] = 0.5f * (war + wbr);
                r[base + 2 + h] = 0.5f * (wai + wbi);
                r[base + 4 + h] = 0.5f * (war - wbr);
                r[base + 6 + h] = 0.5f * (wai - wbi);
            }
        }
    }
    if (j < P2) {
        float* r = g_rec2 + j * 80;
#pragma unroll
        for (int h = 0; h < 2; h++) {
            int k = 2 * j + h;
            bool v = (k < MSZ);
#pragma unroll
            for (int o = 0; o < HD; o++) {
                float war = v ? W2[((2 * o) * MSZ + k) * 2 + 0] : 0.f;
                float wai = v ? W2[((2 * o) * MSZ + k) * 2 + 1] : 0.f;
                float wbr = v ? W2[((2 * o + 1) * MSZ + k) * 2 + 0] : 0.f;
                float wbi = v ? W2[((2 * o + 1) * MSZ + k) * 2 + 1] : 0.f;
                int base = o * 8;
                r[base + 0 + h] = 0.5f * (war + wbr);
                r[base + 2 + h] = 0.5f * (wai + wbi);
                r[base + 4 + h] = 0.5f * (war - wbr);
                r[base + 6 + h] = 0.5f * (wai - wbi);
            }
        }
    }
}

__global__ __launch_bounds__(TB) void eqsonn_kernel(
    const float* __restrict__ x,
    const float* __restrict__ task,
    const float* __restrict__ b1g,
    const float* __restrict__ b2g,
    float* __restrict__ out,
    int S, int Btot) {
    extern __shared__ float sm[];
    float4* E4 = (float4*)sm;                  // 42*HB float4 (row 41 = zero pad)
    float*  R1 = sm + 42 * HB * 4;             // P1*96 floats
    const int P1 = (S + 1) / 2;
    float*  R2 = R1 + P1 * 96;                 // P2*80 floats

    const int t  = threadIdx.x;
    const int g  = t >> 7;                     // 0,1,2
    const int tl = t & (HB - 1);
    const int b  = blockIdx.x * HB + tl;

    // ---- copy packed records into shared ----
    {
        const float4* s1 = (const float4*)g_rec1;
        float4* d1 = (float4*)R1;
        int n1 = P1 * 24;
        for (int i = t; i < n1; i += TB) d1[i] = s1[i];
        const float4* s2 = (const float4*)g_rec2;
        float4* d2 = (float4*)R2;
        for (int i = t; i < P2 * 20; i += TB) d2[i] = s2[i];
    }

    // ---- load E rows (split across 3 groups), zero pad row ----
    if (b < Btot) {
        const float4* xr = (const float4*)(x + (size_t)b * (MSZ * 4));
        int j0 = g * 14;
        int j1 = j0 + 14; if (j1 > MSZ) j1 = MSZ;
        for (int j = j0; j < j1; j++)
            E4[j * HB + tl] = xr[j];
        if (g == 2) E4[41 * HB + tl] = make_float4(0.f, 0.f, 0.f, 0.f);
    }
    __syncthreads();

    const char* Eb = (const char*)E4 + tl * 16;
#define E4AT(off) (*(const float4*)(Eb + (off)))

    // ================= conv2 (k-pairs, sum/diff basis, split 3 ways) ========
    u64 Bsr[HD], Bsi[HD], Bdr[HD], Bdi[HD];
#pragma unroll
    for (int o = 0; o < HD; o++) { Bsr[o] = Bsi[o] = Bdr[o] = Bdi[o] = 0ULL; }
    {
        int j0 = g * 7, j1 = j0 + 7; if (j1 > P2) j1 = P2;
#pragma unroll 2
        for (int j = j0; j < j1; j++) {
            float4 ve = E4AT(j * 4096);
            float4 vo = E4AT(j * 4096 + 2048);
            u64 esr = pk(ve.x + ve.z, vo.x + vo.z);
            u64 esi = pk(ve.y + ve.w, vo.y + vo.w);
            u64 edr = pk(ve.x - ve.z, vo.x - vo.z);
            u64 edi = pk(ve.y - ve.w, vo.y - vo.w);
            u64 nesi = ng(esi), nedi = ng(edi);
            const ulonglong2* w = (const ulonglong2*)(R2 + j * 80);
#pragma unroll
            for (int o = 0; o < HD; o++) {
                ulonglong2 ws = w[2 * o];
                ulonglong2 wd = w[2 * o + 1];
                fma2(Bsr[o], ws.x, esr); fma2(Bsr[o], ws.y, nesi);
                fma2(Bsi[o], ws.x, esi); fma2(Bsi[o], ws.y, esr);
                fma2(Bdr[o], wd.x, edr); fma2(Bdr[o], wd.y, nedi);
                fma2(Bdi[o], wd.x, edi); fma2(Bdi[o], wd.y, edr);
            }
        }
    }
    float bs_r[HD], bs_i[HD], bd_r[HD], bd_i[HD];
#pragma unroll
    for (int o = 0; o < HD; o++) {
        float2 v;
        v = upk(Bsr[o]); bs_r[o] = v.x + v.y;
        v = upk(Bsi[o]); bs_i[o] = v.x + v.y;
        v = upk(Bdr[o]); bd_r[o] = v.x + v.y;
        v = upk(Bdi[o]); bd_i[o] = v.x + v.y;
    }

    // ================= conv1 + pbc (s-pairs, split 3 ways) ==================
    u64 Asr[HD], Asi[HD], Adr[HD], Adi[HD];
#pragma unroll
    for (int o = 0; o < HD; o++) { Asr[o] = Asi[o] = Adr[o] = Adi[o] = 0ULL; }
    u64 psr = 0, psi = 0, pdr = 0, pdi = 0;
    {
        int chunk = (P1 + 2) / 3;
        int j0 = g * chunk;
        int j1 = j0 + chunk; if (j1 > P1) j1 = P1;
#pragma unroll 2
        for (int j = j0; j < j1; j++) {
            const float4* h = (const float4*)(R1 + j * 96);
            float4 he = h[0];
            float4 ho = h[1];
            float4 hc = h[2];

            float Ar_e, Ai_e, nsr_e, nsi_e, ndr_e, ndi_e;
            {
                float4 a = E4AT(__float_as_int(he.x));
                float4 q = E4AT(__float_as_int(he.y));
                float4 n = E4AT(__float_as_int(he.z));
                Ar_e = a.x * q.x + a.y * q.y + a.z * q.z + a.w * q.w;
                Ai_e = a.y * q.x - a.x * q.y + a.w * q.z - a.z * q.w;
                nsr_e = n.x + n.z; nsi_e = n.y + n.w;
                ndr_e = n.x - n.z; ndi_e = n.y - n.w;
            }
            float Ar_o, Ai_o, nsr_o, nsi_o, ndr_o, ndi_o;
            {
                float4 a = E4AT(__float_as_int(ho.x));
                float4 q = E4AT(__float_as_int(ho.y));
                float4 n = E4AT(__float_as_int(ho.z));
                Ar_o = a.x * q.x + a.y * q.y + a.z * q.z + a.w * q.w;
                Ai_o = a.y * q.x - a.x * q.y + a.w * q.z - a.z * q.w;
                nsr_o = n.x + n.z; nsi_o = n.y + n.w;
                ndr_o = n.x - n.z; ndi_o = n.y - n.w;
            }

            u64 TAr = pk(Ar_e, Ar_o), TAi = pk(Ai_e, Ai_o);
            u64 nTAi = ng(TAi);
            u64 ns_r = pk(nsr_e, nsr_o), ns_i = pk(nsi_e, nsi_o);
            u64 nd_r = pk(ndr_e, ndr_o), nd_i = pk(ndi_e, ndi_o);

            u64 Gsr = mul2(TAr, ns_r); fma2(Gsr, nTAi, ns_i);
            u64 Gsi = mul2(TAr, ns_i); fma2(Gsi, TAi, ns_r);
            u64 Gdr = mul2(TAr, nd_r); fma2(Gdr, nTAi, nd_i);
            u64 Gdi = mul2(TAr, nd_i); fma2(Gdi, TAi, nd_r);
            u64 nGsi = ng(Gsi), nGdi = ng(Gdi);

            u64 Cre = pk(hc.x, hc.y), Cim = pk(hc.z, hc.w);
            u64 nCim = ng(Cim);
            fma2(psr, Gsr, Cre); fma2(psr, Gsi, nCim);
            fma2(psi, Gsr, Cim); fma2(psi, Gsi, Cre);
            fma2(pdr, Gdr, Cre); fma2(pdr, Gdi, nCim);
            fma2(pdi, Gdr, Cim); fma2(pdi, Gdi, Cre);

            const ulonglong2* w = (const ulonglong2*)(R1 + j * 96 + 16);
#pragma unroll
            for (int o = 0; o < HD; o++) {
                ulonglong2 ws = w[2 * o];
                ulonglong2 wd = w[2 * o + 1];
                fma2(Asr[o], ws.x, Gsr); fma2(Asr[o], ws.y, nGsi);
                fma2(Asi[o], ws.x, Gsi); fma2(Asi[o], ws.y, Gsr);
                fma2(Adr[o], wd.x, Gdr); fma2(Adr[o], wd.y, nGdi);
                fma2(Adi[o], wd.x, Gdi); fma2(Adi[o], wd.y, Gdr);
            }
        }
    }

    // ---- pack partials (convert back from sum/diff basis) ----
    float my[84];
    {
        float2 v;
        v = upk(psr); float ps_r = v.x + v.y;
        v = upk(psi); float ps_i = v.x + v.y;
        v = upk(pdr); float pd_r = v.x + v.y;
        v = upk(pdi); float pd_i = v.x + v.y;
        my[0] = ps_r + pd_r; my[1] = ps_i + pd_i;
        my[2] = ps_r - pd_r; my[3] = ps_i - pd_i;
#pragma unroll
        for (int o = 0; o < HD; o++) {
            v = upk(Asr[o]); float asr_ = v.x + v.y;
            v = upk(Asi[o]); float asi_ = v.x + v.y;
            v = upk(Adr[o]); float adr_ = v.x + v.y;
            v = upk(Adi[o]); float adi_ = v.x + v.y;
            my[4 + 4 * o + 0] = asr_ + adr_;
            my[4 + 4 * o + 1] = asi_ + adi_;
            my[4 + 4 * o + 2] = asr_ - adr_;
            my[4 + 4 * o + 3] = asi_ - adi_;
        }
#pragma unroll
        for (int o = 0; o < HD; o++) {
            my[44 + 4 * o + 0] = bs_r[o] + bd_r[o];
            my[44 + 4 * o + 1] = bs_i[o] + bd_i[o];
            my[44 + 4 * o + 2] = bs_r[o] - bd_r[o];
            my[44 + 4 * o + 3] = bs_i[o] - bd_i[o];
        }
    }

    // ---- cross-group reduction through smem (reuse R1/R2 region) ----
    __syncthreads();                   // all groups done reading R1/R2
    float* red = R1;
    if (g) {
        float* dst = red + (g - 1) * (HB * 85) + tl * 85;
#pragma unroll
        for (int i = 0; i < 84; i++) dst[i] = my[i];
    }
    __syncthreads();
    if (g) return;

    {
        const float* r1v = red + tl * 85;
        const float* r2v = red + HB * 85 + tl * 85;
#pragma unroll
        for (int i = 0; i < 84; i++) my[i] += r1v[i] + r2v[i];
    }

    // ================= epilogue (group 0 only) =================
    if (b >= Btot) return;
    float tsk = task[(size_t)b * 4];
    float P = exp10f(tsk * 0.1f) * 0.5f;
    const float scl = 3.16227766016837939e-05f;  // 1e-4 / sqrt(10)
    float sc = scl * P * P;
    float4 Ec = E4AT(20 * 2048);

    float tr0 = 0.f, ti0 = 0.f, tr1 = 0.f, ti1 = 0.f;
#pragma unroll
    for (int o = 0; o < HD; o++) {
        float b1r = b1g[2 * o], b1i = b1g[2 * o + 1];
        float b2r = b2g[2 * o], b2i = b2g[2 * o + 1];
        float ar = my[4 + 4 * o + 0] + b1r;
        float ai = my[4 + 4 * o + 1] + b1i;
        float brv = my[44 + 4 * o + 0] + b2r;
        float biv = my[44 + 4 * o + 1] + b2i;
        float rr = 2.f * (ar * brv + ai * biv);
        tr0 += rr * brv; ti0 += rr * biv;

        ar = my[4 + 4 * o + 2] + b1r;
        ai = my[4 + 4 * o + 3] + b1i;
        brv = my[44 + 4 * o + 2] + b2r;
        biv = my[44 + 4 * o + 3] + b2i;
        rr = 2.f * (ar * brv + ai * biv);
        tr1 += rr * brv; ti1 += rr * biv;
    }

    float4 res;
    res.x = Ec.x + P * my[0] + sc * tr0;
    res.y = Ec.y + P * my[1] + sc * ti0;
    res.z = Ec.z + P * my[2] + sc * tr1;
    res.w = Ec.w + P * my[3] + sc * ti1;
    *(float4*)(out + (size_t)b * 4) = res;
}

extern "C" void kernel_launch(void* const* d_in, const int* in_sizes, int n_in,
                              void* d_out, int out_size) {
    const float* x     = (const float*)d_in[0];
    const float* task  = (const float*)d_in[1];
    const float* pbc_C = (const float*)d_in[2];
    const float* W1    = (const float*)d_in[3];
    const float* b1    = (const float*)d_in[4];
    const float* W2    = (const float*)d_in[5];
    const float* b2    = (const float*)d_in[6];
    const int*   m_idx = (const int*)d_in[7];
    const int*   n_idx = (const int*)d_in[8];
    int S = in_sizes[7];
    if (S > 2 * MAXP) S = 2 * MAXP;
    int B = out_size / 4;
    int P1 = (S + 1) / 2;

    // reduction region needs 2*HB*85 floats inside R1+R2: ensure capacity
    size_t recFloats = (size_t)P1 * 96 + (size_t)P2 * 80;
    size_t redFloats = (size_t)2 * HB * 85;
    size_t tailFloats = recFloats > redFloats ? recFloats : redFloats;
    size_t smem = (size_t)(42 * HB) * sizeof(float4) + tailFloats * sizeof(float);
    cudaFuncSetAttribute(eqsonn_kernel,
                         cudaFuncAttributeMaxDynamicSharedMemorySize, (int)smem);

    prep_kernel<<<2, 128>>>(pbc_C, W1, W2, m_idx, n_idx, S);

    int blocks = (B + HB - 1) / HB;
    eqsonn_kernel<<<blocks, TB, smem>>>(x, task, b1, b2, (float*)d_out, S, B);
}

// round 6
// speedup vs baseline: 1.0786x; 1.0786x over previous
#include <cuda_runtime.h>

#define TB   256        // threads per block (2 halves)
#define HB   128        // batch elements per block
#define HD   10         // HDIM
#define MSZ  41         // M
#define MAXP 256        // max s-pairs (S<=512)
#define P2   21         // k-pairs for conv2
#define EST  129        // E row stride in float4 (padded for conflict-free transpose)
#define ERB  (EST*16)   // E row stride in bytes = 2064

typedef unsigned long long u64;

// rec1: per s-pair j, 96 floats:
//  [0..2] byte-offsets (k1,k2,k3)*ERB even s, [3] pad; [4..6] odd s, [7] pad
//  [8,9]=C.re/2 (e,o) [10,11]=C.im/2 (e,o) [12..15] pad
//  [16 + o*8]: Ws.re(e,o), Ws.im(e,o), Wd.re(e,o), Wd.im(e,o)
__device__ float g_rec1[MAXP * 96];
__device__ float g_rec2[P2 * 80];

__device__ __forceinline__ u64 pk(float lo, float hi) {
    u64 r; asm("mov.b64 %0,{%1,%2};" : "=l"(r) : "f"(lo), "f"(hi)); return r;
}
__device__ __forceinline__ float2 upk(u64 v) {
    float2 f; asm("mov.b64 {%0,%1},%2;" : "=f"(f.x), "=f"(f.y) : "l"(v)); return f;
}
__device__ __forceinline__ void fma2(u64 &a, u64 x, u64 y) {
    asm("fma.rn.f32x2 %0,%1,%2,%0;" : "+l"(a) : "l"(x), "l"(y));
}
__device__ __forceinline__ u64 mul2(u64 x, u64 y) {
    u64 r; asm("mul.rn.f32x2 %0,%1,%2;" : "=l"(r) : "l"(x), "l"(y)); return r;
}
__device__ __forceinline__ u64 ng(u64 v) { return v ^ 0x8000000080000000ULL; }

__global__ void prep_kernel(const float* __restrict__ pbc_C,
                            const float* __restrict__ W1,
                            const float* __restrict__ W2,
                            const int*   __restrict__ m_idx,
                            const int*   __restrict__ n_idx,
                            int S) {
    int j = blockIdx.x * blockDim.x + threadIdx.x;
    int P1 = (S + 1) / 2;
    const int c = MSZ / 2;
    if (j < P1) {
        float* r = g_rec1 + j * 96;
        r[3] = 0.f; r[7] = 0.f;
        r[12] = r[13] = r[14] = r[15] = 0.f;
#pragma unroll
        for (int h = 0; h < 2; h++) {
            int s = 2 * j + h;
            bool v = (s < S);
            int m = v ? m_idx[s] : 0;
            int n = v ? n_idx[s] : 0;
            r[4 * h + 0] = __int_as_float(v ? (c + m) * ERB : 0);
            r[4 * h + 1] = __int_as_float(v ? (c + m + n) * ERB : 0);
            r[4 * h + 2] = __int_as_float(v ? (c + n) * ERB : 0);
            r[8 + h]  = v ? 0.5f * pbc_C[2 * s + 0] : 0.f;
            r[10 + h] = v ? 0.5f * pbc_C[2 * s + 1] : 0.f;
#pragma unroll
            for (int o = 0; o < HD; o++) {
                float war = v ? W1[((2 * o) * S + s) * 2 + 0] : 0.f;
                float wai = v ? W1[((2 * o) * S + s) * 2 + 1] : 0.f;
                float wbr = v ? W1[((2 * o + 1) * S + s) * 2 + 0] : 0.f;
                float wbi = v ? W1[((2 * o + 1) * S + s) * 2 + 1] : 0.f;
                int base = 16 + o * 8;
                r[base + 0 + h] = 0.5f * (war + wbr);
                r[base + 2 + h] = 0.5f * (wai + wbi);
                r[base + 4 + h] = 0.5f * (war - wbr);
                r[base + 6 + h] = 0.5f * (wai - wbi);
            }
        }
    }
    if (j < P2) {
        float* r = g_rec2 + j * 80;
#pragma unroll
        for (int h = 0; h < 2; h++) {
            int k = 2 * j + h;
            bool v = (k < MSZ);
#pragma unroll
            for (int o = 0; o < HD; o++) {
                float war = v ? W2[((2 * o) * MSZ + k) * 2 + 0] : 0.f;
                float wai = v ? W2[((2 * o) * MSZ + k) * 2 + 1] : 0.f;
                float wbr = v ? W2[((2 * o + 1) * MSZ + k) * 2 + 0] : 0.f;
                float wbi = v ? W2[((2 * o + 1) * MSZ + k) * 2 + 1] : 0.f;
                int base = o * 8;
                r[base + 0 + h] = 0.5f * (war + wbr);
                r[base + 2 + h] = 0.5f * (wai + wbi);
                r[base + 4 + h] = 0.5f * (war - wbr);
                r[base + 6 + h] = 0.5f * (wai - wbi);
            }
        }
    }
}

__global__ __launch_bounds__(TB) void eqsonn_kernel(
    const float* __restrict__ x,
    const float* __restrict__ task,
    const float* __restrict__ b1g,
    const float* __restrict__ b2g,
    float* __restrict__ out,
    int S, int Btot) {
    extern __shared__ float sm[];
    float4* E4 = (float4*)sm;                  // 42 rows * EST float4 (row 41 = zero)
    float*  R1 = sm + 42 * EST * 4;            // P1*96 floats
    const int P1 = (S + 1) / 2;
    float*  R2 = R1 + P1 * 96;                 // P2*80 floats

    const int t    = threadIdx.x;
    const int half = t >> 7;
    const int tl   = t & (HB - 1);
    const int b    = blockIdx.x * HB + tl;

    // ---- copy packed records into shared ----
    {
        const float4* s1 = (const float4*)g_rec1;
        float4* d1 = (float4*)R1;
        int n1 = P1 * 24;
        for (int i = t; i < n1; i += TB) d1[i] = s1[i];
        const float4* s2 = (const float4*)g_rec2;
        float4* d2 = (float4*)R2;
        for (int i = t; i < P2 * 20; i += TB) d2[i] = s2[i];
    }

    // ---- coalesced transposed E load: read linear float4, scatter [row][elem] ----
    {
        const float4* xb = (const float4*)(x + (size_t)blockIdx.x * HB * (MSZ * 4));
        for (int i = t; i < HB * MSZ; i += TB) {
            int e = i / MSZ;          // batch element within block
            int r = i - e * MSZ;      // symbol row
            E4[r * EST + e] = xb[i];  // read coalesced; write stride-129 conflict-free
        }
        // zero pad row 41 (read by conv2's last k-pair)
        for (int i = t; i < HB; i += TB)
            E4[41 * EST + i] = make_float4(0.f, 0.f, 0.f, 0.f);
    }
    __syncthreads();

    const char* Eb = (const char*)E4 + tl * 16;
#define E4AT(off) (*(const float4*)(Eb + (off)))

    float my[84];

    // ================= conv1 + pbc first (max register headroom) ===========
    {
        u64 Asr[HD], Asi[HD], Adr[HD], Adi[HD];
#pragma unroll
        for (int o = 0; o < HD; o++) { Asr[o] = Asi[o] = Adr[o] = Adi[o] = 0ULL; }
        u64 psr = 0, psi = 0, pdr = 0, pdi = 0;

        int split = (P1 + 1) / 2;
        int j0 = half * split;
        int j1 = half ? P1 : split;
        const float* rp = R1 + (size_t)j0 * 96;
        for (int j = j0; j < j1; j++, rp += 96) {
            const float4* h = (const float4*)rp;
            float4 he = h[0];
            float4 ho = h[1];
            float4 hc = h[2];

            float Ar_e, Ai_e, nsr_e, nsi_e, ndr_e, ndi_e;
            {
                float4 a = E4AT(__float_as_int(he.x));
                float4 q = E4AT(__float_as_int(he.y));
                float4 n = E4AT(__float_as_int(he.z));
                Ar_e = a.x * q.x + a.y * q.y + a.z * q.z + a.w * q.w;
                Ai_e = a.y * q.x - a.x * q.y + a.w * q.z - a.z * q.w;
                nsr_e = n.x + n.z; nsi_e = n.y + n.w;
                ndr_e = n.x - n.z; ndi_e = n.y - n.w;
            }
            float Ar_o, Ai_o, nsr_o, nsi_o, ndr_o, ndi_o;
            {
                float4 a = E4AT(__float_as_int(ho.x));
                float4 q = E4AT(__float_as_int(ho.y));
                float4 n = E4AT(__float_as_int(ho.z));
                Ar_o = a.x * q.x + a.y * q.y + a.z * q.z + a.w * q.w;
                Ai_o = a.y * q.x - a.x * q.y + a.w * q.z - a.z * q.w;
                nsr_o = n.x + n.z; nsi_o = n.y + n.w;
                ndr_o = n.x - n.z; ndi_o = n.y - n.w;
            }

            u64 TAr = pk(Ar_e, Ar_o), TAi = pk(Ai_e, Ai_o);
            u64 nTAi = ng(TAi);
            u64 ns_r = pk(nsr_e, nsr_o), ns_i = pk(nsi_e, nsi_o);
            u64 nd_r = pk(ndr_e, ndr_o), nd_i = pk(ndi_e, ndi_o);

            u64 Gsr = mul2(TAr, ns_r); fma2(Gsr, nTAi, ns_i);
            u64 Gsi = mul2(TAr, ns_i); fma2(Gsi, TAi, ns_r);
            u64 Gdr = mul2(TAr, nd_r); fma2(Gdr, nTAi, nd_i);
            u64 Gdi = mul2(TAr, nd_i); fma2(Gdi, TAi, nd_r);
            u64 nGsi = ng(Gsi), nGdi = ng(Gdi);

            u64 Cre = pk(hc.x, hc.y), Cim = pk(hc.z, hc.w);
            u64 nCim = ng(Cim);
            fma2(psr, Gsr, Cre); fma2(psr, Gsi, nCim);
            fma2(psi, Gsr, Cim); fma2(psi, Gsi, Cre);
            fma2(pdr, Gdr, Cre); fma2(pdr, Gdi, nCim);
            fma2(pdi, Gdr, Cim); fma2(pdi, Gdi, Cre);

            const ulonglong2* w = (const ulonglong2*)(rp + 16);
#pragma unroll
            for (int o = 0; o < HD; o++) {
                ulonglong2 ws = w[2 * o];
                ulonglong2 wd = w[2 * o + 1];
                fma2(Asr[o], ws.x, Gsr); fma2(Asr[o], ws.y, nGsi);
                fma2(Asi[o], ws.x, Gsi); fma2(Asi[o], ws.y, Gsr);
                fma2(Adr[o], wd.x, Gdr); fma2(Adr[o], wd.y, nGdi);
                fma2(Adi[o], wd.x, Gdi); fma2(Adi[o], wd.y, Gdr);
            }
        }

        // collapse conv1 accumulators now (free ~88 regs before conv2)
        float2 v;
        v = upk(psr); float ps_r = v.x + v.y;
        v = upk(psi); float ps_i = v.x + v.y;
        v = upk(pdr); float pd_r = v.x + v.y;
        v = upk(pdi); float pd_i = v.x + v.y;
        my[0] = ps_r + pd_r; my[1] = ps_i + pd_i;
        my[2] = ps_r - pd_r; my[3] = ps_i - pd_i;
#pragma unroll
        for (int o = 0; o < HD; o++) {
            v = upk(Asr[o]); float asr_ = v.x + v.y;
            v = upk(Asi[o]); float asi_ = v.x + v.y;
            v = upk(Adr[o]); float adr_ = v.x + v.y;
            v = upk(Adi[o]); float adi_ = v.x + v.y;
            my[4 + 4 * o + 0] = asr_ + adr_;
            my[4 + 4 * o + 1] = asi_ + adi_;
            my[4 + 4 * o + 2] = asr_ - adr_;
            my[4 + 4 * o + 3] = asi_ - adi_;
        }
    }

    // ================= conv2 (short loop) =================
    {
        u64 Bsr[HD], Bsi[HD], Bdr[HD], Bdi[HD];
#pragma unroll
        for (int o = 0; o < HD; o++) { Bsr[o] = Bsi[o] = Bdr[o] = Bdi[o] = 0ULL; }
        int j0 = half * 11, j1 = half ? P2 : 11;
        const float* rp = R2 + (size_t)j0 * 80;
        for (int j = j0; j < j1; j++, rp += 80) {
            float4 ve = E4AT(2 * j * ERB);
            float4 vo = E4AT((2 * j + 1) * ERB);
            u64 esr = pk(ve.x + ve.z, vo.x + vo.z);
            u64 esi = pk(ve.y + ve.w, vo.y + vo.w);
            u64 edr = pk(ve.x - ve.z, vo.x - vo.z);
            u64 edi = pk(ve.y - ve.w, vo.y - vo.w);
            u64 nesi = ng(esi), nedi = ng(edi);
            const ulonglong2* w = (const ulonglong2*)rp;
#pragma unroll
            for (int o = 0; o < HD; o++) {
                ulonglong2 ws = w[2 * o];
                ulonglong2 wd = w[2 * o + 1];
                fma2(Bsr[o], ws.x, esr); fma2(Bsr[o], ws.y, nesi);
                fma2(Bsi[o], ws.x, esi); fma2(Bsi[o], ws.y, esr);
                fma2(Bdr[o], wd.x, edr); fma2(Bdr[o], wd.y, nedi);
                fma2(Bdi[o], wd.x, edi); fma2(Bdi[o], wd.y, edr);
            }
        }
#pragma unroll
        for (int o = 0; o < HD; o++) {
            float2 v;
            v = upk(Bsr[o]); float bsr_ = v.x + v.y;
            v = upk(Bsi[o]); float bsi_ = v.x + v.y;
            v = upk(Bdr[o]); float bdr_ = v.x + v.y;
            v = upk(Bdi[o]); float bdi_ = v.x + v.y;
            my[44 + 4 * o + 0] = bsr_ + bdr_;
            my[44 + 4 * o + 1] = bsi_ + bdi_;
            my[44 + 4 * o + 2] = bsr_ - bdr_;
            my[44 + 4 * o + 3] = bsi_ - bdi_;
        }
    }

    // ---- cross-half reduction through smem (reuse R1 region) ----
    __syncthreads();
    float* red = R1;
    if (half) {
        float* dst = red + tl * 85;
#pragma unroll
        for (int i = 0; i < 84; i++) dst[i] = my[i];
    }
    __syncthreads();
    if (half) return;

    {
        const float* r1v = red + tl * 85;
#pragma unroll
        for (int i = 0; i < 84; i++) my[i] += r1v[i];
    }

    // ================= epilogue (half 0 only) =================
    if (b >= Btot) return;
    float tsk = task[(size_t)b * 4];
    float P = exp10f(tsk * 0.1f) * 0.5f;
    const float scl = 3.16227766016837939e-05f;  // 1e-4 / sqrt(10)
    float sc = scl * P * P;
    float4 Ec = E4AT(20 * ERB);

    float tr0 = 0.f, ti0 = 0.f, tr1 = 0.f, ti1 = 0.f;
#pragma unroll
    for (int o = 0; o < HD; o++) {
        float b1r = b1g[2 * o], b1i = b1g[2 * o + 1];
        float b2r = b2g[2 * o], b2i = b2g[2 * o + 1];
        float ar = my[4 + 4 * o + 0] + b1r;
        float ai = my[4 + 4 * o + 1] + b1i;
        float brv = my[44 + 4 * o + 0] + b2r;
        float biv = my[44 + 4 * o + 1] + b2i;
        float rr = 2.f * (ar * brv + ai * biv);
        tr0 += rr * brv; ti0 += rr * biv;

        ar = my[4 + 4 * o + 2] + b1r;
        ai = my[4 + 4 * o + 3] + b1i;
        brv = my[44 + 4 * o + 2] + b2r;
        biv = my[44 + 4 * o + 3] + b2i;
        rr = 2.f * (ar * brv + ai * biv);
        tr1 += rr * brv; ti1 += rr * biv;
    }

    float4 res;
    res.x = Ec.x + P * my[0] + sc * tr0;
    res.y = Ec.y + P * my[1] + sc * ti0;
    res.z = Ec.z + P * my[2] + sc * tr1;
    res.w = Ec.w + P * my[3] + sc * ti1;
    *(float4*)(out + (size_t)b * 4) = res;
}

extern "C" void kernel_launch(void* const* d_in, const int* in_sizes, int n_in,
                              void* d_out, int out_size) {
    const float* x     = (const float*)d_in[0];
    const float* task  = (const float*)d_in[1];
    const float* pbc_C = (const float*)d_in[2];
    const float* W1    = (const float*)d_in[3];
    const float* b1    = (const float*)d_in[4];
    const float* W2    = (const float*)d_in[5];
    const float* b2    = (const float*)d_in[6];
    const int*   m_idx = (const int*)d_in[7];
    const int*   n_idx = (const int*)d_in[8];
    int S = in_sizes[7];
    if (S > 2 * MAXP) S = 2 * MAXP;
    int B = out_size / 4;
    int P1 = (S + 1) / 2;

    size_t recFloats = (size_t)P1 * 96 + (size_t)P2 * 80;
    size_t redFloats = (size_t)HB * 85;
    size_t tailFloats = recFloats > redFloats ? recFloats : redFloats;
    size_t smem = (size_t)(42 * EST) * sizeof(float4) + tailFloats * sizeof(float);
    cudaFuncSetAttribute(eqsonn_kernel,
                         cudaFuncAttributeMaxDynamicSharedMemorySize, (int)smem);

    prep_kernel<<<2, 128>>>(pbc_C, W1, W2, m_idx, n_idx, S);

    int blocks = (B + HB - 1) / HB;
    eqsonn_kernel<<<blocks, TB, smem>>>(x, task, b1, b2, (float*)d_out, S, B);
}